// round 9
// baseline (speedup 1.0000x reference)
#include <cuda_runtime.h>

#define NGRID 20
#define NPTS  8000           // 20^3
#define TD    39             // offsets -19..19
#define DA_MAX 9             // |ia-ib| > 9 -> min d2 > 40 -> weight < 2e-9
#define D2_CUT 40.0f
#define NB    128            // persistent blocks (co-resident on 148 SMs)

// Scratch (no allocation allowed in kernel_launch)
__device__ float g_partial[NGRID * NPTS];   // [ib][pt]
__device__ float g_bsum[NGRID * NGRID];     // per (ia,ib) pair sum
__device__ int   g_count;                   // arrival counter (self-resetting)
__device__ int   g_done;                    // departure counter (self-resetting)

// ---------------------------------------------------------------------------
// Single persistent kernel.
//   Phase 1: each block loops vp = bid + k*NB over all 400 (ia,ib) pairs,
//            running the frozen conv body per live pair.
//   Sync:    per-thread threadfence -> block barrier -> t0 atomic arrive +
//            volatile spin -> block barrier -> threadfence (release/acquire).
//   Phase 2: blocks 0..19 gather ib-window partials (hot L2); S computed by
//            warp 0 ONLY (full warp, fixed order) and broadcast via smem —
//            this fixes the R8 partial-warp shfl UB.
// ---------------------------------------------------------------------------
__global__ void __launch_bounds__(400) kde_kernel(
    const float* __restrict__ p, const float* __restrict__ cov_inv,
    float* __restrict__ out)
{
    __shared__ __align__(16) float sT[TD * TD + 3];
    __shared__ __align__(16) float sp[NGRID * NGRID];
    __shared__ __align__(16) float sred[1600];
    __shared__ float sS;

    const int t   = threadIdx.x;
    const int bid = blockIdx.x;

    const float a00 = cov_inv[0], a01 = cov_inv[1], a02 = cov_inv[2];
    const float a11 = cov_inv[4], a12 = cov_inv[5], a22 = cov_inv[8];

    const float s00 = a00 - a02 * a02 / a22;
    const float s01 = a01 - a02 * a12 / a22;
    const float s11 = a11 - a12 * a12 / a22;

    const int gidx = t / 100;            // jb-split group 0..3
    const int sidx = t - gidx * 100;     // output slot 0..99
    const int ja   = sidx / 5;
    const int ka0  = (sidx - ja * 5) * 4;

    // ---------------- Phase 1: conv over assigned pairs ----------------
    for (int vp = bid; vp < NGRID * NGRID; vp += NB) {
        const int ia = vp / NGRID;
        const int ib = vp - ia * NGRID;
        const int da = ia - ib;

        if (da < -DA_MAX || da > DA_MAX) {
            if (t == 0) g_bsum[vp] = 0.0f;
            continue;
        }

        __syncthreads();   // protect smem reuse across pair iterations

        sp[t] = p[ib * 400 + t];

        if (t < 156) {     // table slab via 2-FMUL exp recurrence
            int row = t >> 2, seg = t & 3;
            float dy = (float)(row - 19);
            int   dz0 = -19 + seg * 10;
            int   cnt = (seg == 3) ? 9 : 10;
            float dx = (float)da;
            float c1 = 2.0f * (a02 * dx + a12 * dy);
            float c0 = a00 * dx * dx + 2.0f * a01 * dx * dy + a11 * dy * dy;
            float z  = (float)dz0;
            float g  = expf(-0.5f * (c0 + c1 * z + a22 * z * z));
            float r  = expf(-0.5f * (c1 + a22 * (2.0f * z + 1.0f)));
            float B  = expf(-a22);
            float* dst = &sT[row * TD + (dz0 + 19)];
            for (int i = 0; i < cnt; i++) { dst[i] = g; g *= r; r *= B; }
        }
        __syncthreads();

        float fx  = (float)da;
        float bq  = s01 * fx;
        float disc = bq * bq - s11 * (s00 * fx * fx - D2_CUT);
        int jb_lo = 0, jb_hi = -1;
        if (disc > 0.0f) {
            float sq  = sqrtf(disc);
            float dyl = (-bq - sq) / s11;
            float dyh = (-bq + sq) / s11;
            jb_lo = max(0,  (int)ceilf ((float)ja - dyh - 0.01f));
            jb_hi = min(19, (int)floorf((float)ja - dyl + 0.01f));
        }

        float acc0 = 0.f, acc1 = 0.f, acc2 = 0.f, acc3 = 0.f;

        for (int jb = jb_lo + gidx; jb <= jb_hi; jb += 4) {
            const float* row = &sT[(ja - jb + 19) * TD];

            float pv[20];
            {
                const float4* pr4 = reinterpret_cast<const float4*>(&sp[jb * NGRID]);
#pragma unroll
                for (int u = 0; u < 5; u++) {
                    float4 v = pr4[u];
                    pv[4*u] = v.x; pv[4*u+1] = v.y; pv[4*u+2] = v.z; pv[4*u+3] = v.w;
                }
            }

            float w0 = row[ka0 + 19];
            float w1 = row[ka0 + 20];
            float w2 = row[ka0 + 21];
            float w3 = row[ka0 + 22];
#pragma unroll
            for (int kb = 0; kb < 20; kb++) {
                float pvk = pv[kb];
                acc0 = fmaf(w0, pvk, acc0);
                acc1 = fmaf(w1, pvk, acc1);
                acc2 = fmaf(w2, pvk, acc2);
                acc3 = fmaf(w3, pvk, acc3);
                if (kb < 19) { w3 = w2; w2 = w1; w1 = w0; w0 = row[ka0 + 18 - kb]; }
            }
        }

        *reinterpret_cast<float4*>(&sred[gidx * 400 + sidx * 4]) =
            make_float4(acc0, acc1, acc2, acc3);
        __syncthreads();

        float val = sred[t] + sred[400 + t] + sred[800 + t] + sred[1200 + t];
        g_partial[ib * NPTS + ia * 400 + t] = val;
        __syncthreads();

        sred[t] = val;
        if (t < 112) sred[400 + t] = 0.0f;
        __syncthreads();
        for (int k = 256; k > 32; k >>= 1) {
            if (t < k) sred[t] += sred[t + k];
            __syncthreads();
        }
        if (t < 32) {
            float v = sred[t] + sred[t + 32];
#pragma unroll
            for (int off = 16; off > 0; off >>= 1)
                v += __shfl_down_sync(0xffffffffu, v, off);
            if (t == 0) g_bsum[vp] = v;
        }
    }

    // ---------------- grid-wide sync (all NB blocks resident) ----------------
    __threadfence();
    __syncthreads();
    if (t == 0) {
        atomicAdd(&g_count, 1);
        while (*(volatile int*)&g_count < NB) { __nanosleep(32); }
    }
    __syncthreads();
    __threadfence();

    // ---------------- Phase 2: gather + normalize (blocks 0..19) -------------
    if (bid < NGRID) {                       // block-uniform guard
        const int pt = bid * 400 + t;        // < 8000 for all t
        const int ia = bid;
        const int lo = max(0, ia - DA_MAX);
        const int hi = min(19, ia + DA_MAX);

        // issue gather loads first (independent of S)
        float gv[2 * DA_MAX + 1];
#pragma unroll
        for (int k = 0; k < 2 * DA_MAX + 1; k++) {
            int ib = lo + k;
            gv[k] = (ib <= hi) ? g_partial[ib * NPTS + pt] : 0.0f;
        }

        // S computed by warp 0 ONLY (full warp — partial-warp shfl was the
        // R8 bug), broadcast via smem.
        if (t < 32) {
            float v = 0.0f;
#pragma unroll
            for (int i = 0; i < 13; i++) {   // 13*32 = 416 >= 400, fixed order
                int idx = t + 32 * i;
                if (idx < 400) v += g_bsum[idx];
            }
#pragma unroll
            for (int off = 16; off > 0; off >>= 1)
                v += __shfl_xor_sync(0xffffffffu, v, off);
            if (t == 0) sS = v;
        }
        __syncthreads();
        const float S = sS;

        float s = 0.0f;
#pragma unroll
        for (int k = 0; k < 2 * DA_MAX + 1; k++) s += gv[k];
        out[pt] = s / S;
    }

    // ---------------- counter reset (graph-replay safe) ----------------
    __syncthreads();
    if (t == 0) {
        int d = atomicAdd(&g_done, 1);
        if (d == NB - 1) {
            g_count = 0;
            g_done  = 0;
            __threadfence();
        }
    }
}

extern "C" void kernel_launch(void* const* d_in, const int* in_sizes, int n_in,
                              void* d_out, int out_size) {
    const float* space_probs = (const float*)d_in[0];  // 8000 floats
    const float* cov_inv     = (const float*)d_in[1];  // 9 floats
    float* out = (float*)d_out;                        // 8000 floats

    kde_kernel<<<NB, 400>>>(space_probs, cov_inv, out);
}

// round 10
// speedup vs baseline: 1.3220x; 1.3220x over previous
#include <cuda_runtime.h>

#define NGRID 20
#define NPTS  8000           // 20^3
#define TD    39             // offsets -19..19
#define DA_MAX 7             // da^2/2 > 28 -> plane pruned (tail mass ~4e-6)
#define D2_CUT 28.0f

// Scratch (no allocation allowed in kernel_launch)
__device__ float g_partial[NGRID * NPTS];   // [ib][pt]
__device__ float g_bsum[NGRID * NGRID];     // per (ia,ib) block sum

// ---------------------------------------------------------------------------
// Kernel A (R7 structure, frozen): one (ia,ib) pair per block. 400 threads =
// 100 output-threads (4 outputs each, sliding table window) x 4 jb-split
// groups. Table slab via 2-FMUL exp recurrence. Block reduces its own
// normalizer contribution into g_bsum.
// ---------------------------------------------------------------------------
__global__ void __launch_bounds__(400) conv_kernel(
    const float* __restrict__ p, const float* __restrict__ cov_inv)
{
    __shared__ __align__(16) float sT[TD * TD + 3];
    __shared__ __align__(16) float sp[NGRID * NGRID];
    __shared__ __align__(16) float sred[1600];

    const int t  = threadIdx.x;
    const int ia = blockIdx.x;
    const int ib = blockIdx.y;
    const int da = ia - ib;

    if (da < -DA_MAX || da > DA_MAX) {
        if (t == 0) g_bsum[ia * NGRID + ib] = 0.0f;
        return;
    }

    const float a00 = cov_inv[0], a01 = cov_inv[1], a02 = cov_inv[2];
    const float a11 = cov_inv[4], a12 = cov_inv[5], a22 = cov_inv[8];

    sp[t] = p[ib * 400 + t];

    if (t < 156) {
        int row = t >> 2, seg = t & 3;
        float dy = (float)(row - 19);
        int   dz0 = -19 + seg * 10;
        int   cnt = (seg == 3) ? 9 : 10;
        float dx = (float)da;
        float c1 = 2.0f * (a02 * dx + a12 * dy);
        float c0 = a00 * dx * dx + 2.0f * a01 * dx * dy + a11 * dy * dy;
        float z  = (float)dz0;
        float g  = expf(-0.5f * (c0 + c1 * z + a22 * z * z));
        float r  = expf(-0.5f * (c1 + a22 * (2.0f * z + 1.0f)));
        float B  = expf(-a22);
        float* dst = &sT[row * TD + (dz0 + 19)];
        for (int i = 0; i < cnt; i++) { dst[i] = g; g *= r; r *= B; }
    }
    __syncthreads();

    const int gidx = t / 100;
    const int s    = t - gidx * 100;
    const int ja   = s / 5;
    const int ka0  = (s - ja * 5) * 4;

    float s00 = a00 - a02 * a02 / a22;
    float s01 = a01 - a02 * a12 / a22;
    float s11 = a11 - a12 * a12 / a22;
    float fx  = (float)da;
    float bq  = s01 * fx;
    float disc = bq * bq - s11 * (s00 * fx * fx - D2_CUT);
    int jb_lo = 0, jb_hi = -1;
    if (disc > 0.0f) {
        float sq  = sqrtf(disc);
        float dyl = (-bq - sq) / s11;
        float dyh = (-bq + sq) / s11;
        jb_lo = max(0,  (int)ceilf ((float)ja - dyh - 0.01f));
        jb_hi = min(19, (int)floorf((float)ja - dyl + 0.01f));
    }

    float acc0 = 0.f, acc1 = 0.f, acc2 = 0.f, acc3 = 0.f;

    for (int jb = jb_lo + gidx; jb <= jb_hi; jb += 4) {
        const float* row = &sT[(ja - jb + 19) * TD];

        float pv[20];
        {
            const float4* pr4 = reinterpret_cast<const float4*>(&sp[jb * NGRID]);
#pragma unroll
            for (int u = 0; u < 5; u++) {
                float4 v = pr4[u];
                pv[4*u] = v.x; pv[4*u+1] = v.y; pv[4*u+2] = v.z; pv[4*u+3] = v.w;
            }
        }

        float w0 = row[ka0 + 19];
        float w1 = row[ka0 + 20];
        float w2 = row[ka0 + 21];
        float w3 = row[ka0 + 22];
#pragma unroll
        for (int kb = 0; kb < 20; kb++) {
            float pvk = pv[kb];
            acc0 = fmaf(w0, pvk, acc0);
            acc1 = fmaf(w1, pvk, acc1);
            acc2 = fmaf(w2, pvk, acc2);
            acc3 = fmaf(w3, pvk, acc3);
            if (kb < 19) { w3 = w2; w2 = w1; w1 = w0; w0 = row[ka0 + 18 - kb]; }
        }
    }

    *reinterpret_cast<float4*>(&sred[gidx * 400 + s * 4]) =
        make_float4(acc0, acc1, acc2, acc3);
    __syncthreads();

    float val = sred[t] + sred[400 + t] + sred[800 + t] + sred[1200 + t];
    g_partial[ib * NPTS + ia * 400 + t] = val;
    __syncthreads();

    sred[t] = val;
    if (t < 112) sred[400 + t] = 0.0f;
    __syncthreads();
    for (int k = 256; k > 32; k >>= 1) {
        if (t < k) sred[t] += sred[t + k];
        __syncthreads();
    }
    if (t < 32) {
        float v = sred[t] + sred[t + 32];
#pragma unroll
        for (int off = 16; off > 0; off >>= 1)
            v += __shfl_down_sync(0xffffffffu, v, off);
        if (t == 0) g_bsum[ia * NGRID + ib] = v;
    }
}

// ---------------------------------------------------------------------------
// Kernel B (R7 structure, frozen): 64 blocks x 128 threads, one point per
// thread. Gather loads issued first (now 15 of them); S folded barrier-free,
// warp-redundant over FULL warps (fixed order -> deterministic).
// ---------------------------------------------------------------------------
__global__ void __launch_bounds__(128) finish_kernel(float* __restrict__ out) {
    const int t    = threadIdx.x;
    const int lane = t & 31;
    const int pt   = blockIdx.x * 128 + t;

    const int ia = (pt < NPTS) ? (pt / 400) : 0;
    const int lo = max(0, ia - DA_MAX);
    const int hi = min(19, ia + DA_MAX);

    float gv[2 * DA_MAX + 1];
#pragma unroll
    for (int k = 0; k < 2 * DA_MAX + 1; k++) {   // 15 predicated batched loads
        int ib = lo + k;
        gv[k] = (pt < NPTS && ib <= hi) ? g_partial[ib * NPTS + pt] : 0.0f;
    }

    float v = 0.0f;
#pragma unroll
    for (int i = 0; i < 13; i++) {               // 13*32 = 416 >= 400
        int idx = lane + 32 * i;
        if (idx < 400) v += g_bsum[idx];
    }
#pragma unroll
    for (int off = 16; off > 0; off >>= 1)
        v += __shfl_xor_sync(0xffffffffu, v, off);
    const float S = v;

    if (pt >= NPTS) return;

    float s = 0.0f;
#pragma unroll
    for (int k = 0; k < 2 * DA_MAX + 1; k++) s += gv[k];
    out[pt] = s / S;
}

extern "C" void kernel_launch(void* const* d_in, const int* in_sizes, int n_in,
                              void* d_out, int out_size) {
    const float* space_probs = (const float*)d_in[0];  // 8000 floats
    const float* cov_inv     = (const float*)d_in[1];  // 9 floats
    float* out = (float*)d_out;                        // 8000 floats

    conv_kernel  <<<dim3(NGRID, NGRID), 400>>>(space_probs, cov_inv);
    finish_kernel<<<64, 128>>>(out);
}